// round 8
// baseline (speedup 1.0000x reference)
#include <cuda_runtime.h>
#include <cuda_bf16.h>

// Problem constants
#define BDIM 2048   // batch rows
#define SDIM 1024   // support vectors
#define FDIM 64     // features

// Tiling
#define BM 64       // rows per block = 32 lane-pairs (r, r+32)
#define BN 32       // support cols per block
#define TN 8        // cols per warp (4 warps x 8 = 32 = BN)
#define NTHREADS 128
#define SSPLIT 32   // grid.y; each block covers 1024/32 = 32 S cols

// Precomputed half-angle trig tables in bf16.
// X pre-PAIRED per 64-row block: rows r = blk*64+q and r+32:
//   g_Xb[f*1024 + blk*32 + q] = { bf16x2(cos_r, cos_{r+32}), bf16x2(sin_r, sin_{r+32}) }
//   -> one lane-unique LDS.64 per f yields both packed X operands.
// S pre-SPLATTED: g_Scb[f*1024 + j] = bf16x2(cos_j, cos_j); g_Ssb likewise.
//   -> read DIRECTLY from global via broadcast LDG.128 (L1-resident; no smem).
__device__ __align__(16) uint2    g_Xb[FDIM * (BDIM / 2)];   // 512 KB
__device__ __align__(16) unsigned g_Scb[FDIM * SDIM];        // 256 KB
__device__ __align__(16) unsigned g_Ssb[FDIM * SDIM];        // 256 KB

static __device__ __forceinline__ __nv_bfloat162 u2bf2(unsigned u) {
    return *reinterpret_cast<__nv_bfloat162*>(&u);
}

// ---------------------------------------------------------------------------
// Kernel A: precompute bf16 trig tables + initialize out[i] = b[0]
// ---------------------------------------------------------------------------
__global__ void precompute_kernel(const float* __restrict__ X,
                                  const float* __restrict__ S,
                                  const float* __restrict__ b,
                                  float* __restrict__ out) {
    int idx = blockIdx.x * blockDim.x + threadIdx.x;

    const int NX2 = FDIM * (BDIM / 2);   // 65536 X pair entries
    const int NS  = FDIM * SDIM;         // 65536

    if (idx < NX2) {
        int f = idx >> 10;               // / 1024
        int e = idx & 1023;
        int blk = e >> 5;
        int q = e & 31;
        int r0 = blk * 64 + q;
        float v0 = X[r0 * FDIM + f];
        float v1 = X[(r0 + 32) * FDIM + f];
        float s0, c0, s1, c1;
        __sincosf(0.5f * v0, &s0, &c0);
        __sincosf(0.5f * v1, &s1, &c1);
        __nv_bfloat162 cp = __floats2bfloat162_rn(c0, c1);  // (lo=r, hi=r+32)
        __nv_bfloat162 sp = __floats2bfloat162_rn(s0, s1);
        g_Xb[idx] = make_uint2(*reinterpret_cast<unsigned*>(&cp),
                               *reinterpret_cast<unsigned*>(&sp));
    } else if (idx < NX2 + NS) {
        int e = idx - NX2;
        int f = e >> 10;
        int j = e & (SDIM - 1);
        float v = S[j * FDIM + f];
        float s, c;
        __sincosf(0.5f * v, &s, &c);
        __nv_bfloat162 cc = __floats2bfloat162_rn(c, c);
        __nv_bfloat162 ss = __floats2bfloat162_rn(s, s);
        g_Scb[e] = *reinterpret_cast<unsigned*>(&cc);
        g_Ssb[e] = *reinterpret_cast<unsigned*>(&ss);
    }

    if (idx < BDIM) {
        out[idx] = b[0];                 // global atomics accumulate on top
    }
}

// ---------------------------------------------------------------------------
// Kernel B: grid (2048/64, 32) = 1024 blocks, 128 threads, 8 blocks/SM
//   (smem 16.25 KB, regs capped 64) -> 32 warps/SM, SINGLE WAVE (1184 slots).
//   Lane owns row pair (rowbase+lane, rowbase+lane+32) packed in bf16x2.
//   Warp w owns cols [w*8, w*8+8).
//   Inner iter: 1 LDS.64 (X, lane-unique) + 4 LDG.128 (S, broadcast, L1-hit)
//   + 24 bf16x2 math ops covering 64 rows x 8 cols = 512 positions.
// ---------------------------------------------------------------------------
__global__ __launch_bounds__(NTHREADS, 8)
void qkr_main_kernel(const float* __restrict__ W,
                     float* __restrict__ out) {
    __shared__ __align__(16) uint2 sX[FDIM * 32];     // 16 KB  [f*32 + q]

    const int tid  = threadIdx.x;
    const int lane = tid & 31;
    const int warp = tid >> 5;          // 0..3
    const int col0 = warp * TN;         // 0,8,16,24
    const int jbase = blockIdx.y * BN;  // 32 support cols for this block

    // X fill: 1024 uint4, 8 per thread, fully coalesced
    #pragma unroll
    for (int e4 = tid; e4 < 1024; e4 += NTHREADS) {
        int f = e4 >> 4;
        int k = e4 & 15;
        ((uint4*)sX)[e4] =
            *(const uint4*)&g_Xb[f * (BDIM / 2) + blockIdx.x * 32 + k * 2];
    }
    __syncthreads();

    // p[c] = bf16x2 running product of cos((x - s_c)/2) over the lane's row pair
    __nv_bfloat162 p[TN];
    const __nv_bfloat162 one2 = __float2bfloat162_rn(1.0f);
    #pragma unroll
    for (int c = 0; c < TN; c++) p[c] = one2;

    const unsigned scol = jbase + col0;   // uniform across warp

    #pragma unroll 4
    for (int f = 0; f < FDIM; f++) {
        uint2 xv = sX[f * 32 + lane];                    // lane-unique LDS.64
        __nv_bfloat162 xc = u2bf2(xv.x);
        __nv_bfloat162 xs = u2bf2(xv.y);

        // S: broadcast LDG.128 (all lanes same address, L1-resident)
        uint4 ca = __ldg((const uint4*)&g_Scb[f * SDIM + scol]);
        uint4 cb = __ldg((const uint4*)&g_Scb[f * SDIM + scol + 4]);
        uint4 sa = __ldg((const uint4*)&g_Ssb[f * SDIM + scol]);
        uint4 sb = __ldg((const uint4*)&g_Ssb[f * SDIM + scol + 4]);
        unsigned scu[TN] = { ca.x, ca.y, ca.z, ca.w, cb.x, cb.y, cb.z, cb.w };
        unsigned ssu[TN] = { sa.x, sa.y, sa.z, sa.w, sb.x, sb.y, sb.z, sb.w };

        #pragma unroll
        for (int c = 0; c < TN; c++) {
            __nv_bfloat162 t = __hmul2(xc, u2bf2(scu[c]));   // xc*sc
            t = __hfma2(xs, u2bf2(ssu[c]), t);               // + xs*ss
            p[c] = __hmul2(p[c], t);                         // running product
        }
    }

    // Epilogue in f32: K = (prod cos)^2 ; acc += W[j] * K
    float acc0 = 0.0f, acc1 = 0.0f;
    #pragma unroll
    for (int c = 0; c < TN; c++) {
        float w  = __ldg(&W[jbase + col0 + c]);
        float lo = __low2float(p[c]);
        float hi = __high2float(p[c]);
        acc0 = fmaf(w, lo * lo, acc0);
        acc1 = fmaf(w, hi * hi, acc1);
    }

    // Direct global accumulation (REDG, no return). 4 warps x 32 y-blocks
    // hit each row over the whole grid -> 128 spread-in-time adds/address.
    atomicAdd(&out[blockIdx.x * BM + lane],      acc0);
    atomicAdd(&out[blockIdx.x * BM + lane + 32], acc1);
}

// ---------------------------------------------------------------------------
extern "C" void kernel_launch(void* const* d_in, const int* in_sizes, int n_in,
                              void* d_out, int out_size) {
    const float* X = (const float*)d_in[0];   // [2048, 64]
    const float* S = (const float*)d_in[1];   // [1024, 64]
    const float* W = (const float*)d_in[2];   // [1, 1024]
    const float* b = (const float*)d_in[3];   // [1]
    float* out = (float*)d_out;               // [2048]

    {
        int total = FDIM * (BDIM / 2) + FDIM * SDIM;   // 131072
        int threads = 256;
        int blocks = (total + threads - 1) / threads;
        precompute_kernel<<<blocks, threads>>>(X, S, b, out);
    }
    {
        dim3 grid(BDIM / BM, SSPLIT);   // (32, 32) = 1024 blocks, single wave
        qkr_main_kernel<<<grid, NTHREADS>>>(W, out);
    }
}

// round 9
// speedup vs baseline: 1.1443x; 1.1443x over previous
#include <cuda_runtime.h>
#include <cuda_bf16.h>

// Problem constants
#define BDIM 2048   // batch rows
#define SDIM 1024   // support vectors
#define FDIM 64     // features

// Tiling
#define BM 64       // rows per block = 32 lane-pairs (r, r+32)
#define BN 32       // support cols per block (one chunk)
#define TN 8        // cols per warp (4 warps x 8 = 32 = BN)
#define NTHREADS 128
#define SSPLIT 32   // grid.y; each block covers 1024/32 = 32 S cols

// Precomputed half-angle trig tables in bf16.
// X pre-PAIRED per 64-row block: rows r = blk*64+q and r+32:
//   g_Xb[f*1024 + blk*32 + q] = { bf16x2(cos_r, cos_{r+32}), bf16x2(sin_r, sin_{r+32}) }
//   -> one lane-unique LDS.64 per f yields both packed X operands.
// S pre-SPLATTED: g_Scb[f*1024 + j] = bf16x2(cos_j, cos_j); g_Ssb likewise.
//   -> one broadcast LDS.128 yields 4 ready splatted columns.
__device__ __align__(16) uint2    g_Xb[FDIM * (BDIM / 2)];   // 512 KB
__device__ __align__(16) unsigned g_Scb[FDIM * SDIM];        // 256 KB
__device__ __align__(16) unsigned g_Ssb[FDIM * SDIM];        // 256 KB

static __device__ __forceinline__ __nv_bfloat162 u2bf2(unsigned u) {
    return *reinterpret_cast<__nv_bfloat162*>(&u);
}

// ---------------------------------------------------------------------------
// Kernel A: precompute bf16 trig tables + initialize out[i] = b[0]
// ---------------------------------------------------------------------------
__global__ void precompute_kernel(const float* __restrict__ X,
                                  const float* __restrict__ S,
                                  const float* __restrict__ b,
                                  float* __restrict__ out) {
    int idx = blockIdx.x * blockDim.x + threadIdx.x;

    const int NX2 = FDIM * (BDIM / 2);   // 65536 X pair entries
    const int NS  = FDIM * SDIM;         // 65536

    if (idx < NX2) {
        int f = idx >> 10;               // / 1024
        int e = idx & 1023;
        int blk = e >> 5;
        int q = e & 31;
        int r0 = blk * 64 + q;
        float v0 = X[r0 * FDIM + f];
        float v1 = X[(r0 + 32) * FDIM + f];
        float s0, c0, s1, c1;
        __sincosf(0.5f * v0, &s0, &c0);
        __sincosf(0.5f * v1, &s1, &c1);
        __nv_bfloat162 cp = __floats2bfloat162_rn(c0, c1);  // (lo=r, hi=r+32)
        __nv_bfloat162 sp = __floats2bfloat162_rn(s0, s1);
        g_Xb[idx] = make_uint2(*reinterpret_cast<unsigned*>(&cp),
                               *reinterpret_cast<unsigned*>(&sp));
    } else if (idx < NX2 + NS) {
        int e = idx - NX2;
        int f = e >> 10;
        int j = e & (SDIM - 1);
        float v = S[j * FDIM + f];
        float s, c;
        __sincosf(0.5f * v, &s, &c);
        __nv_bfloat162 cc = __floats2bfloat162_rn(c, c);
        __nv_bfloat162 ss = __floats2bfloat162_rn(s, s);
        g_Scb[e] = *reinterpret_cast<unsigned*>(&cc);
        g_Ssb[e] = *reinterpret_cast<unsigned*>(&ss);
    }

    if (idx < BDIM) {
        out[idx] = b[0];                 // global atomics accumulate on top
    }
}

// ---------------------------------------------------------------------------
// Kernel B: grid (2048/64, 32) = 1024 blocks, 128 threads (4 warps).
//   smem 32.25 KB + min-7-blocks launch bound -> 7 blocks/SM, capacity
//   7*148 = 1036 >= 1024  => TRUE SINGLE WAVE, 28 warps/SM steady state.
//   Lane owns row pair (rowbase+lane, rowbase+lane+32) packed in bf16x2.
//   Warp w owns cols [w*8, w*8+8): S loads broadcast LDS.128 (1 wf each).
//   Inner iter: 1 LDS.64 (X) + 4 LDS.128 (S) + 24 bf16x2 math ops
//   covering 64 rows x 8 cols = 512 positions.
// ---------------------------------------------------------------------------
__global__ __launch_bounds__(NTHREADS, 7)
void qkr_main_kernel(const float* __restrict__ W,
                     float* __restrict__ out) {
    __shared__ __align__(16) uint2    sX[FDIM * 32];     // 16 KB  [f*32 + q]
    __shared__ __align__(16) unsigned sSc[FDIM * BN];    //  8 KB  [f*32 + c]
    __shared__ __align__(16) unsigned sSs[FDIM * BN];    //  8 KB

    const int tid  = threadIdx.x;
    const int lane = tid & 31;
    const int warp = tid >> 5;          // 0..3
    const int col0 = warp * TN;         // 0,8,16,24 (uint4-aligned)
    const int jbase = blockIdx.y * BN;  // 32 support cols for this block

    // Vectorized fills. X: 1024 uint4 (8/thread); S: 512 uint4 each (4/thread).
    #pragma unroll
    for (int e4 = tid; e4 < 1024; e4 += NTHREADS) {
        int f = e4 >> 4;
        int k = e4 & 15;
        ((uint4*)sX)[e4] =
            *(const uint4*)&g_Xb[f * (BDIM / 2) + blockIdx.x * 32 + k * 2];
    }
    #pragma unroll
    for (int e4 = tid; e4 < 512; e4 += NTHREADS) {
        int f = e4 >> 3;
        int k = e4 & 7;
        ((uint4*)sSc)[e4] = *(const uint4*)&g_Scb[f * SDIM + jbase + k * 4];
        ((uint4*)sSs)[e4] = *(const uint4*)&g_Ssb[f * SDIM + jbase + k * 4];
    }
    __syncthreads();

    // p[c] = bf16x2 running product of cos((x - s_c)/2) over the lane's row pair
    __nv_bfloat162 p[TN];
    const __nv_bfloat162 one2 = __float2bfloat162_rn(1.0f);
    #pragma unroll
    for (int c = 0; c < TN; c++) p[c] = one2;

    #pragma unroll 4
    for (int f = 0; f < FDIM; f++) {
        uint2 xv = sX[f * 32 + lane];                    // lane-unique LDS.64
        __nv_bfloat162 xc = u2bf2(xv.x);
        __nv_bfloat162 xs = u2bf2(xv.y);

        // broadcast LDS.128: 4 splatted cols each (1 wavefront per load)
        uint4 ca = *(const uint4*)&sSc[f * BN + col0];
        uint4 cb = *(const uint4*)&sSc[f * BN + col0 + 4];
        uint4 sa = *(const uint4*)&sSs[f * BN + col0];
        uint4 sb = *(const uint4*)&sSs[f * BN + col0 + 4];
        unsigned scu[TN] = { ca.x, ca.y, ca.z, ca.w, cb.x, cb.y, cb.z, cb.w };
        unsigned ssu[TN] = { sa.x, sa.y, sa.z, sa.w, sb.x, sb.y, sb.z, sb.w };

        #pragma unroll
        for (int c = 0; c < TN; c++) {
            __nv_bfloat162 t = __hmul2(xc, u2bf2(scu[c]));   // xc*sc
            t = __hfma2(xs, u2bf2(ssu[c]), t);               // + xs*ss
            p[c] = __hmul2(p[c], t);                         // running product
        }
    }

    // Epilogue in f32: K = (prod cos)^2 ; acc += W[j] * K
    float acc0 = 0.0f, acc1 = 0.0f;
    #pragma unroll
    for (int c = 0; c < TN; c++) {
        float w  = __ldg(&W[jbase + col0 + c]);
        float lo = __low2float(p[c]);
        float hi = __high2float(p[c]);
        acc0 = fmaf(w, lo * lo, acc0);
        acc1 = fmaf(w, hi * hi, acc1);
    }

    // Direct global accumulation (REDG, no return). 128 adds per address,
    // spread in time across the grid -> negligible.
    atomicAdd(&out[blockIdx.x * BM + lane],      acc0);
    atomicAdd(&out[blockIdx.x * BM + lane + 32], acc1);
}

// ---------------------------------------------------------------------------
extern "C" void kernel_launch(void* const* d_in, const int* in_sizes, int n_in,
                              void* d_out, int out_size) {
    const float* X = (const float*)d_in[0];   // [2048, 64]
    const float* S = (const float*)d_in[1];   // [1024, 64]
    const float* W = (const float*)d_in[2];   // [1, 1024]
    const float* b = (const float*)d_in[3];   // [1]
    float* out = (float*)d_out;               // [2048]

    {
        int total = FDIM * (BDIM / 2) + FDIM * SDIM;   // 131072
        int threads = 256;
        int blocks = (total + threads - 1) / threads;
        precompute_kernel<<<blocks, threads>>>(X, S, b, out);
    }
    {
        dim3 grid(BDIM / BM, SSPLIT);   // (32, 32) = 1024 blocks, single wave
        qkr_main_kernel<<<grid, NTHREADS>>>(W, out);
    }
}

// round 10
// speedup vs baseline: 1.2229x; 1.0687x over previous
#include <cuda_runtime.h>
#include <cuda_bf16.h>

// Problem constants
#define BDIM 2048   // batch rows
#define SDIM 1024   // support vectors
#define FDIM 64     // features

// Tiling
#define BM 64       // rows per block = 32 lane-pairs (r, r+32)
#define BN 32       // support cols per block (one chunk)
#define TN 8        // cols per warp (4 warps x 8 = 32 = BN)
#define NTHREADS 128
#define SSPLIT 32   // grid.y; each block covers 1024/32 = 32 S cols

// Precomputed half-angle trig tables in bf16.
// X pre-PAIRED per 64-row block: rows r = blk*64+q and r+32:
//   g_Xb[f*1024 + blk*32 + q] = { bf16x2(cos_r, cos_{r+32}), bf16x2(sin_r, sin_{r+32}) }
//   -> one lane-unique LDS.64 per f yields both packed X operands.
// S NON-SPLATTED, cos+sin packed per col: g_Sb[f*1024 + j] = bf16x2(cos_j, sin_j)
//   -> one broadcast LDS.128 yields 4 cols; splat via half-lane selection
//      (__low2bfloat162/__high2bfloat162 -> HFMA2 .H0_H0 operand modifiers).
__device__ __align__(16) uint2    g_Xb[FDIM * (BDIM / 2)];   // 512 KB
__device__ __align__(16) unsigned g_Sb[FDIM * SDIM];         // 256 KB

static __device__ __forceinline__ __nv_bfloat162 u2bf2(unsigned u) {
    return *reinterpret_cast<__nv_bfloat162*>(&u);
}

// ---------------------------------------------------------------------------
// Kernel A: precompute bf16 trig tables + initialize out[i] = b[0]
// ---------------------------------------------------------------------------
__global__ void precompute_kernel(const float* __restrict__ X,
                                  const float* __restrict__ S,
                                  const float* __restrict__ b,
                                  float* __restrict__ out) {
    int idx = blockIdx.x * blockDim.x + threadIdx.x;

    const int NX2 = FDIM * (BDIM / 2);   // 65536 X pair entries
    const int NS  = FDIM * SDIM;         // 65536

    if (idx < NX2) {
        int f = idx >> 10;               // / 1024
        int e = idx & 1023;
        int blk = e >> 5;
        int q = e & 31;
        int r0 = blk * 64 + q;
        float v0 = X[r0 * FDIM + f];
        float v1 = X[(r0 + 32) * FDIM + f];
        float s0, c0, s1, c1;
        __sincosf(0.5f * v0, &s0, &c0);
        __sincosf(0.5f * v1, &s1, &c1);
        __nv_bfloat162 cp = __floats2bfloat162_rn(c0, c1);  // (lo=r, hi=r+32)
        __nv_bfloat162 sp = __floats2bfloat162_rn(s0, s1);
        g_Xb[idx] = make_uint2(*reinterpret_cast<unsigned*>(&cp),
                               *reinterpret_cast<unsigned*>(&sp));
    } else if (idx < NX2 + NS) {
        int e = idx - NX2;
        int f = e >> 10;
        int j = e & (SDIM - 1);
        float v = S[j * FDIM + f];
        float s, c;
        __sincosf(0.5f * v, &s, &c);
        __nv_bfloat162 cs = __floats2bfloat162_rn(c, s);    // (lo=cos, hi=sin)
        g_Sb[e] = *reinterpret_cast<unsigned*>(&cs);
    }

    if (idx < BDIM) {
        out[idx] = b[0];                 // global atomics accumulate on top
    }
}

// ---------------------------------------------------------------------------
// Kernel B: grid (2048/64, 32) = 1024 blocks, 128 threads (4 warps).
//   smem 24.25 KB -> 8 blocks/SM, capacity 8*148 = 1184 >= 1024
//   => TRUE SINGLE WAVE, 32 warps/SM (8 per SMSP).
//   Lane owns row pair (rowbase+lane, rowbase+lane+32) packed in bf16x2.
//   Warp w owns cols [w*8, w*8+8).
//   Inner iter: 1 LDS.64 (X, lane-unique) + 2 broadcast LDS.128 (S)
//   + 24 bf16x2 math ops (half-lane splat folded) per 512 positions.
// ---------------------------------------------------------------------------
__global__ __launch_bounds__(NTHREADS, 8)
void qkr_main_kernel(const float* __restrict__ W,
                     float* __restrict__ out) {
    __shared__ __align__(16) uint2    sX[FDIM * 32];   // 16 KB  [f*32 + q]
    __shared__ __align__(16) unsigned sS[FDIM * BN];   //  8 KB  [f*32 + c]

    const int tid  = threadIdx.x;
    const int lane = tid & 31;
    const int warp = tid >> 5;          // 0..3
    const int col0 = warp * TN;         // 0,8,16,24 (uint4-aligned)
    const int jbase = blockIdx.y * BN;  // 32 support cols for this block

    // Vectorized fills. X: 1024 uint4 (8/thread); S: 512 uint4 (4/thread).
    #pragma unroll
    for (int e4 = tid; e4 < 1024; e4 += NTHREADS) {
        int f = e4 >> 4;
        int k = e4 & 15;
        ((uint4*)sX)[e4] =
            *(const uint4*)&g_Xb[f * (BDIM / 2) + blockIdx.x * 32 + k * 2];
    }
    #pragma unroll
    for (int e4 = tid; e4 < 512; e4 += NTHREADS) {
        int f = e4 >> 3;
        int k = e4 & 7;
        ((uint4*)sS)[e4] = *(const uint4*)&g_Sb[f * SDIM + jbase + k * 4];
    }
    __syncthreads();

    // p[c] = bf16x2 running product of cos((x - s_c)/2) over the lane's row pair
    __nv_bfloat162 p[TN];
    const __nv_bfloat162 one2 = __float2bfloat162_rn(1.0f);
    #pragma unroll
    for (int c = 0; c < TN; c++) p[c] = one2;

    #pragma unroll 4
    for (int f = 0; f < FDIM; f++) {
        uint2 xv = sX[f * 32 + lane];                    // lane-unique LDS.64
        __nv_bfloat162 xc = u2bf2(xv.x);
        __nv_bfloat162 xs = u2bf2(xv.y);

        // S: 2 broadcast LDS.128 -> 8 cols of (cos,sin) packed bf16x2
        uint4 sa = *(const uint4*)&sS[f * BN + col0];
        uint4 sb = *(const uint4*)&sS[f * BN + col0 + 4];
        unsigned su[TN] = { sa.x, sa.y, sa.z, sa.w, sb.x, sb.y, sb.z, sb.w };

        #pragma unroll
        for (int c = 0; c < TN; c++) {
            __nv_bfloat162 sv = u2bf2(su[c]);
            // half-lane splats: lo = (cos,cos), hi = (sin,sin); ptxas folds
            // these into HFMA2/HMUL2 .H0_H0/.H1_H1 operand selectors.
            __nv_bfloat162 t = __hmul2(xc, __low2bfloat162(sv));   // xc*sc
            t = __hfma2(xs, __high2bfloat162(sv), t);              // + xs*ss
            p[c] = __hmul2(p[c], t);                               // product
        }
    }

    // Epilogue in f32: K = (prod cos)^2 ; acc += W[j] * K
    float acc0 = 0.0f, acc1 = 0.0f;
    #pragma unroll
    for (int c = 0; c < TN; c++) {
        float w  = __ldg(&W[jbase + col0 + c]);
        float lo = __low2float(p[c]);
        float hi = __high2float(p[c]);
        acc0 = fmaf(w, lo * lo, acc0);
        acc1 = fmaf(w, hi * hi, acc1);
    }

    // Direct global accumulation (REDG, no return). 128 adds per address,
    // spread in time across the grid -> negligible.
    atomicAdd(&out[blockIdx.x * BM + lane],      acc0);
    atomicAdd(&out[blockIdx.x * BM + lane + 32], acc1);
}

// ---------------------------------------------------------------------------
extern "C" void kernel_launch(void* const* d_in, const int* in_sizes, int n_in,
                              void* d_out, int out_size) {
    const float* X = (const float*)d_in[0];   // [2048, 64]
    const float* S = (const float*)d_in[1];   // [1024, 64]
    const float* W = (const float*)d_in[2];   // [1, 1024]
    const float* b = (const float*)d_in[3];   // [1]
    float* out = (float*)d_out;               // [2048]

    {
        int total = FDIM * (BDIM / 2) + FDIM * SDIM;   // 131072
        int threads = 256;
        int blocks = (total + threads - 1) / threads;
        precompute_kernel<<<blocks, threads>>>(X, S, b, out);
    }
    {
        dim3 grid(BDIM / BM, SSPLIT);   // (32, 32) = 1024 blocks, single wave
        qkr_main_kernel<<<grid, NTHREADS>>>(W, out);
    }
}

// round 12
// speedup vs baseline: 1.3350x; 1.0917x over previous
#include <cuda_runtime.h>
#include <cuda_bf16.h>

// Problem constants
#define BDIM 2048   // batch rows
#define SDIM 1024   // support vectors
#define FDIM 64     // features
#define FP   32     // feature PAIRS (FDIM/2)

// Tiling
#define BM 64       // rows per block = 32 lane-pairs (r, r+32)
#define BN 32       // support cols per block
#define TN 8        // cols per warp (4 warps x 8 = 32 = BN)
#define NTHREADS 128
#define SSPLIT 32   // grid.y; each block covers 1024/32 = 32 S cols

// Feature-pair trig tables (exact identity):
//   A_f = (x_f - s_f)/2;  cosA0*cosA1 = 1/2[cos(P-Q) + cos(M-N)]
//   P=(x0+x1)/2, M=(x0-x1)/2 (per row);  Q=(s0+s1)/2, N=(s0-s1)/2 (per col)
// X table, PAIRED over rows (r, r+32), 1/2 folded in:
//   g_Xp[fp*1024 + blk*32 + q] = uint4 {
//     bf16x2(.5cosP_r, .5cosP_r32), bf16x2(.5sinP...), bf16x2(.5cosM...), bf16x2(.5sinM...) }
// S table: g_Sp[fp*1024 + j] = uint2 { bf16x2(cosQ, sinQ), bf16x2(cosN, sinN) }
__device__ __align__(16) uint4 g_Xp[FP * (BDIM / 2)];   // 512 KB
__device__ __align__(16) uint2 g_Sp[FP * SDIM];         // 256 KB

static __device__ __forceinline__ __nv_bfloat162 u2bf2(unsigned u) {
    return *reinterpret_cast<__nv_bfloat162*>(&u);
}
static __device__ __forceinline__ unsigned bf2u(__nv_bfloat162 v) {
    return *reinterpret_cast<unsigned*>(&v);
}

// ---------------------------------------------------------------------------
// Kernel A: precompute feature-pair trig tables + initialize out[i] = b[0]
// ---------------------------------------------------------------------------
__global__ void precompute_kernel(const float* __restrict__ X,
                                  const float* __restrict__ S,
                                  const float* __restrict__ b,
                                  float* __restrict__ out) {
    int idx = blockIdx.x * blockDim.x + threadIdx.x;

    const int NXP = FP * (BDIM / 2);   // 32768 uint4 entries
    const int NSP = FP * SDIM;         // 32768 uint2 entries

    if (idx < NXP) {
        int fp = idx >> 10;            // / 1024
        int e  = idx & 1023;
        int blk = e >> 5;
        int q   = e & 31;
        int r0 = blk * 64 + q;         // rows r0 and r0+32
        int f0 = fp * 2;

        float cP[2], sP[2], cM[2], sM[2];
        #pragma unroll
        for (int m = 0; m < 2; m++) {
            int r = r0 + m * 32;
            float x0 = X[r * FDIM + f0];
            float x1 = X[r * FDIM + f0 + 1];
            float P = 0.5f * (x0 + x1);
            float M = 0.5f * (x0 - x1);
            float sp_, cp_, sm_, cm_;
            __sincosf(P, &sp_, &cp_);
            __sincosf(M, &sm_, &cm_);
            cP[m] = 0.5f * cp_;  sP[m] = 0.5f * sp_;   // fold the 1/2
            cM[m] = 0.5f * cm_;  sM[m] = 0.5f * sm_;
        }
        uint4 v;
        v.x = bf2u(__floats2bfloat162_rn(cP[0], cP[1]));
        v.y = bf2u(__floats2bfloat162_rn(sP[0], sP[1]));
        v.z = bf2u(__floats2bfloat162_rn(cM[0], cM[1]));
        v.w = bf2u(__floats2bfloat162_rn(sM[0], sM[1]));
        g_Xp[idx] = v;
    } else if (idx < NXP + NSP) {
        int e  = idx - NXP;
        int fp = e >> 10;
        int j  = e & (SDIM - 1);
        int f0 = fp * 2;
        float s0 = S[j * FDIM + f0];
        float s1 = S[j * FDIM + f0 + 1];
        float Q = 0.5f * (s0 + s1);
        float N = 0.5f * (s0 - s1);
        float sq, cq, sn, cn;
        __sincosf(Q, &sq, &cq);
        __sincosf(N, &sn, &cn);
        uint2 v;
        v.x = bf2u(__floats2bfloat162_rn(cq, sq));
        v.y = bf2u(__floats2bfloat162_rn(cn, sn));
        g_Sp[e] = v;
    }

    if (idx < BDIM) {
        out[idx] = b[0];               // global atomics accumulate on top
    }
}

// ---------------------------------------------------------------------------
// Kernel B: grid (2048/64, 32) = 1024 blocks, 128 threads (4 warps).
//   smem 24.25 KB -> 8 blocks/SM; capacity 1184 >= 1024 => single wave.
//   Lane owns row pair (rowbase+lane, rowbase+lane+32) packed in bf16x2.
//   Warp w owns cols [w*8, w*8+8).
//   Inner iter (one FEATURE PAIR, 512 positions):
//     1 lane-unique LDS.128 (X) + 4 broadcast LDS.128 (S, 2 cols each)
//     + 40 bf16x2 ops (5 per col: mul + 3 fma + product mul).
//   Running product p equals prod_f cos((x_f - s_f)/2) EXACTLY as before.
// ---------------------------------------------------------------------------
__global__ __launch_bounds__(NTHREADS, 8)
void qkr_main_kernel(const float* __restrict__ W,
                     float* __restrict__ out) {
    __shared__ __align__(16) uint4 sX[FP * 32];   // 16 KB  [fp*32 + q]
    __shared__ __align__(16) uint2 sS[FP * BN];   //  8 KB  [fp*32 + c]

    const int tid  = threadIdx.x;
    const int lane = tid & 31;
    const int warp = tid >> 5;          // 0..3
    const int col0 = warp * TN;         // 0,8,16,24
    const int jbase = blockIdx.y * BN;  // 32 support cols for this block

    // Fills: X 1024 uint4 (8/thread).
    #pragma unroll
    for (int e = tid; e < FP * 32; e += NTHREADS) {
        int fp = e >> 5;
        int q  = e & 31;
        sX[e] = g_Xp[fp * (BDIM / 2) + blockIdx.x * 32 + q];
    }
    // S fill: FP*BN = 1024 uint2 = 512 uint4 (4/thread). Each uint4 covers
    // 2 consecutive cols; k = 0..15 covers all 32 cols per feature pair.
    #pragma unroll
    for (int e4 = tid; e4 < 512; e4 += NTHREADS) {
        int fp = e4 >> 4;
        int k  = e4 & 15;
        ((uint4*)sS)[e4] = *(const uint4*)&g_Sp[fp * SDIM + jbase + k * 2];
    }
    __syncthreads();

    // p[c] = bf16x2 running product of cos((x-s)/2) over the lane's row pair
    __nv_bfloat162 p[TN];
    const __nv_bfloat162 one2 = __float2bfloat162_rn(1.0f);
    #pragma unroll
    for (int c = 0; c < TN; c++) p[c] = one2;

    #pragma unroll 4
    for (int fp = 0; fp < FP; fp++) {
        uint4 xv = sX[fp * 32 + lane];          // lane-unique LDS.128
        __nv_bfloat162 hcP = u2bf2(xv.x);       // .5*cosP over row pair
        __nv_bfloat162 hsP = u2bf2(xv.y);
        __nv_bfloat162 hcM = u2bf2(xv.z);
        __nv_bfloat162 hsM = u2bf2(xv.w);

        // S: 4 broadcast LDS.128, 2 cols per load
        const uint2* srow = &sS[fp * BN + col0];
        uint4 sa = *(const uint4*)&srow[0];
        uint4 sb = *(const uint4*)&srow[2];
        uint4 sc = *(const uint4*)&srow[4];
        uint4 sd = *(const uint4*)&srow[6];
        unsigned qn[TN * 2] = { sa.x, sa.y, sa.z, sa.w,
                                sb.x, sb.y, sb.z, sb.w,
                                sc.x, sc.y, sc.z, sc.w,
                                sd.x, sd.y, sd.z, sd.w };

        #pragma unroll
        for (int c = 0; c < TN; c++) {
            __nv_bfloat162 qv = u2bf2(qn[c * 2]);       // (cosQ, sinQ)
            __nv_bfloat162 nv = u2bf2(qn[c * 2 + 1]);   // (cosN, sinN)
            // term = .5cos(P-Q) + .5cos(M-N); half-lane splats fold into ops
            __nv_bfloat162 t = __hmul2(hcP, __low2bfloat162(qv));
            t = __hfma2(hsP, __high2bfloat162(qv), t);
            t = __hfma2(hcM, __low2bfloat162(nv), t);
            t = __hfma2(hsM, __high2bfloat162(nv), t);
            p[c] = __hmul2(p[c], t);                    // running product
        }
    }

    // Epilogue in f32: K = (prod cos)^2 ; acc += W[j] * K
    float acc0 = 0.0f, acc1 = 0.0f;
    #pragma unroll
    for (int c = 0; c < TN; c++) {
        float w  = __ldg(&W[jbase + col0 + c]);
        float lo = __low2float(p[c]);
        float hi = __high2float(p[c]);
        acc0 = fmaf(w, lo * lo, acc0);
        acc1 = fmaf(w, hi * hi, acc1);
    }

    // Direct global accumulation (REDG). 128 adds/address spread in time.
    atomicAdd(&out[blockIdx.x * BM + lane],      acc0);
    atomicAdd(&out[blockIdx.x * BM + lane + 32], acc1);
}

// ---------------------------------------------------------------------------
extern "C" void kernel_launch(void* const* d_in, const int* in_sizes, int n_in,
                              void* d_out, int out_size) {
    const float* X = (const float*)d_in[0];   // [2048, 64]
    const float* S = (const float*)d_in[1];   // [1024, 64]
    const float* W = (const float*)d_in[2];   // [1, 1024]
    const float* b = (const float*)d_in[3];   // [1]
    float* out = (float*)d_out;               // [2048]

    {
        int total = FP * (BDIM / 2) + FP * SDIM;   // 65536
        int threads = 256;
        int blocks = (total + threads - 1) / threads;
        precompute_kernel<<<blocks, threads>>>(X, S, b, out);
    }
    {
        dim3 grid(BDIM / BM, SSPLIT);   // (32, 32) = 1024 blocks, single wave
        qkr_main_kernel<<<grid, NTHREADS>>>(W, out);
    }
}